// round 5
// baseline (speedup 1.0000x reference)
#include <cuda_runtime.h>
#include <cuda_bf16.h>
#include <cstdint>

#define S_LEN  512
#define BATCH  64
#define HID    1024
#define LAYERS 3
#define BH     (BATCH*HID)     // 65536
#define NTILE  32              // unit tiles per layer (32 hidden units each)
#define BROWS  192             // weight rows per tile: 96 Wih + 96 Whh
#define KCH    32              // K per chunk
#define CHUNKS 32              // 1024 / 32
#define DEPTH  4               // cp.async ring depth

#define SR     40              // smem row stride in halfs (80B, pad vs bank conflict)
// slot rows: [0,64)Ax_hi [64,128)Ax_lo [128,192)Ah_hi [192,256)Ah_lo
//            [256,352)Wih_hi [352,448)Wih_lo [448,544)Whh_hi [544,640)Whh_lo
#define SLOT_HALFS (640*SR)            // 25600
#define SLOT_BYTES (SLOT_HALFS*2)      // 51200
#define SMEM_REQ (1024 + DEPTH*SLOT_BYTES)   // 205824 B

typedef __nv_bfloat16 bf16;

// ---------------- device scratch (no runtime allocation) -------------------
__device__ bf16 g_xhi[(size_t)S_LEN*BH];
__device__ bf16 g_xlo[(size_t)S_LEN*BH];
__device__ bf16 g_wBhi[(size_t)LAYERS*NTILE*BROWS*HID];   // per-CTA-tile contiguous
__device__ bf16 g_wBlo[(size_t)LAYERS*NTILE*BROWS*HID];
__device__ float g_h  [LAYERS*2*BH];          // fp32 h, parity double buffer
__device__ bf16  g_hhi[LAYERS*2*BH];
__device__ bf16  g_hlo[LAYERS*2*BH];

// ---------------- helpers ----------------------------------------------------
__device__ __forceinline__ void ldsm4(uint32_t r[4], const bf16* p) {
    uint32_t a = (uint32_t)__cvta_generic_to_shared(p);
    asm volatile("ldmatrix.sync.aligned.m8n8.x4.shared.b16 {%0,%1,%2,%3}, [%4];"
                 : "=r"(r[0]), "=r"(r[1]), "=r"(r[2]), "=r"(r[3]) : "r"(a));
}

__device__ __forceinline__ void mma16816(float c[4], const uint32_t a[4],
                                         uint32_t b0, uint32_t b1) {
    asm volatile("mma.sync.aligned.m16n8k16.row.col.f32.bf16.bf16.f32 "
                 "{%0,%1,%2,%3}, {%4,%5,%6,%7}, {%8,%9}, {%0,%1,%2,%3};"
                 : "+f"(c[0]), "+f"(c[1]), "+f"(c[2]), "+f"(c[3])
                 : "r"(a[0]), "r"(a[1]), "r"(a[2]), "r"(a[3]), "r"(b0), "r"(b1));
}

__device__ __forceinline__ void split2(float v, bf16& hi, bf16& lo) {
    hi = __float2bfloat16_rn(v);
    lo = __float2bfloat16_rn(v - __bfloat162float(hi));
}

__device__ __forceinline__ void cp16(bf16* dst, const bf16* src) {
    uint32_t d = (uint32_t)__cvta_generic_to_shared(dst);
    asm volatile("cp.async.cg.shared.global [%0], [%1], 16;" :: "r"(d), "l"(src));
}

// ---------------- prep kernels ----------------------------------------------
__global__ void split_weights_kernel(const float* __restrict__ wih,
                                     const float* __restrict__ whh) {
    size_t i = (size_t)blockIdx.x * blockDim.x + threadIdx.x;
    if (i >= (size_t)LAYERS * 3 * HID * HID) return;
    int k = (int)(i % HID);
    size_t row = i / HID;
    int l = (int)(row / (3 * HID));
    int r = (int)(row % (3 * HID));
    int g = r >> 10, u = r & 1023;            // gate 0..2, unit 0..1023
    int tile = u >> 5, uu = u & 31;
    size_t dih = (((size_t)(l * NTILE + tile)) * BROWS + g * 32 + uu) * HID + k;
    size_t dhh = dih + (size_t)96 * HID;
    bf16 hi, lo;
    split2(wih[i], hi, lo); g_wBhi[dih] = hi; g_wBlo[dih] = lo;
    split2(whh[i], hi, lo); g_wBhi[dhh] = hi; g_wBlo[dhh] = lo;
}

__global__ void split_x_kernel(const float* __restrict__ x) {
    size_t i = (size_t)blockIdx.x * blockDim.x + threadIdx.x;
    if (i >= (size_t)S_LEN * BH) return;
    bf16 hi, lo;
    split2(x[i], hi, lo); g_xhi[i] = hi; g_xlo[i] = lo;
}

__global__ void init_h_kernel(const float* __restrict__ h0) {
    size_t i = (size_t)blockIdx.x * blockDim.x + threadIdx.x;
    if (i >= (size_t)LAYERS * BH) return;
    int l = (int)(i / BH);
    size_t j = i % BH;
    float v = h0[i];
    size_t dst = ((size_t)l * 2 + 0) * BH + j;
    g_h[dst] = v;
    bf16 hi, lo;
    split2(v, hi, lo); g_hhi[dst] = hi; g_hlo[dst] = lo;
}

// ---------------- chunk loader ------------------------------------------------
// Loads one K=32 chunk of everything: Ax(hi,lo), Ah(hi,lo), W(ih/hh, hi/lo).
__device__ __forceinline__ void load_chunk(
    bf16* slot, int kb,
    const bf16* __restrict__ Axh, const bf16* __restrict__ Axl,
    const bf16* __restrict__ Ahh, const bf16* __restrict__ Ahl,
    const bf16* __restrict__ Bh,  const bf16* __restrict__ Bl,   // 192 x 1024 tile
    int tid)
{
    // A: 4 regions x 64 rows, 32 halfs each (4 x 16B)
#pragma unroll
    for (int i = tid; i < 1024; i += 512) {
        int row = i >> 2, c16 = i & 3;
        int reg = row >> 6, r = row & 63;
        const bf16* src = (reg == 0) ? Axh : (reg == 1) ? Axl : (reg == 2) ? Ahh : Ahl;
        cp16(slot + row * SR + c16 * 8, src + (size_t)r * HID + kb + c16 * 8);
    }
    // W: 4 regions x 96 rows
#pragma unroll
    for (int i = tid; i < 1536; i += 512) {
        int row = i >> 2, c16 = i & 3;
        int reg = row / 96, r = row - reg * 96;
        const bf16* src = (reg & 1) ? Bl : Bh;
        size_t grow = (size_t)((reg >> 1) * 96 + r) * HID + kb + c16 * 8;
        cp16(slot + (256 + row) * SR + c16 * 8, src + grow);
    }
}

// ---------------- fused GRU step (layer-pipelined wavefront) ---------------
// grid (32, LAYERS), 512 threads = 16 warps: wp(path) x 4 wm x 2 wn.
__global__ __launch_bounds__(512) void gru_step_kernel(
    int gs, const float* __restrict__ bih, const float* __restrict__ bhh,
    float* __restrict__ out)
{
    const int l = blockIdx.y;
    const int t = gs - l;
    if (t < 0 || t >= S_LEN) return;

    const int tile = blockIdx.x;
    const int u0   = tile * 32;
    const int tid  = threadIdx.x;
    const int lane = tid & 31;
    const int wid  = tid >> 5;
    const int wp   = wid >> 3;          // 0: x-path (gi), 1: h-path (gh)
    const int wm   = (wid >> 1) & 3;    // batch rows 16*wm
    const int wn   = wid & 1;           // gate cols 48*wn

    extern __shared__ __align__(16) unsigned char smem_raw[];
    uint32_t dyn_u = (uint32_t)__cvta_generic_to_shared(smem_raw);
    uint32_t s0u   = (dyn_u + 1023u) & ~1023u;
    bf16* sbase = (bf16*)(smem_raw + (s0u - dyn_u));

    const int par = t & 1;
    const bf16 *Axh, *Axl;
    if (l == 0) {
        Axh = g_xhi + (size_t)t * BH;  Axl = g_xlo + (size_t)t * BH;
    } else {
        size_t o = ((size_t)(l - 1) * 2 + (par ^ 1)) * BH;   // h_{l-1}[t]
        Axh = g_hhi + o;  Axl = g_hlo + o;
    }
    size_t oh = ((size_t)l * 2 + par) * BH;                   // h_l[t-1]
    const bf16* Ahh = g_hhi + oh;
    const bf16* Ahl = g_hlo + oh;
    size_t ob = ((size_t)(l * NTILE + tile)) * BROWS * HID;
    const bf16* Bh = g_wBhi + ob;
    const bf16* Bl = g_wBlo + ob;

    float acc[6][4];
#pragma unroll
    for (int j = 0; j < 6; ++j)
#pragma unroll
        for (int q = 0; q < 4; ++q) acc[j][q] = 0.f;

    // fragment addressing (per warp, within its path's regions)
    const int aBase = wp * 128;                   // A hi rows; lo = +64
    const int wBase = 256 + wp * 192;             // W hi rows; lo = +96
    const int rowA  = wm * 16 + (lane & 15);
    const int ahalf = (lane >> 4) * 8;
    const int rowB  = (lane & 7) + ((lane & 16) ? 8 : 0);
    const int bhalf = (lane & 8) ? 8 : 0;

    // ---- prologue: prefetch chunks 0..2 ----
#pragma unroll
    for (int c = 0; c < DEPTH - 1; ++c) {
        load_chunk(sbase + (size_t)c * SLOT_HALFS, c * KCH,
                   Axh, Axl, Ahh, Ahl, Bh, Bl, tid);
        asm volatile("cp.async.commit_group;" ::: "memory");
    }

    // ---- main loop: 32 chunks, depth-4 ring ----
    for (int c = 0; c < CHUNKS; ++c) {
        asm volatile("cp.async.wait_group 2;" ::: "memory");
        __syncthreads();
        const int nc = c + DEPTH - 1;
        if (nc < CHUNKS)
            load_chunk(sbase + (size_t)(nc & (DEPTH - 1)) * SLOT_HALFS, nc * KCH,
                       Axh, Axl, Ahh, Ahl, Bh, Bl, tid);
        asm volatile("cp.async.commit_group;" ::: "memory");   // drain-safe

        const bf16* slot = sbase + (size_t)(c & (DEPTH - 1)) * SLOT_HALFS;
#pragma unroll
        for (int ks = 0; ks < 2; ++ks) {
            uint32_t ah[4], al[4];
            ldsm4(ah, slot + (aBase + rowA) * SR + ks * 16 + ahalf);
            ldsm4(al, slot + (aBase + 64 + rowA) * SR + ks * 16 + ahalf);
#pragma unroll
            for (int j = 0; j < 3; ++j) {
                uint32_t bh[4], bl[4];
                int br = wBase + wn * 48 + j * 16 + rowB;
                ldsm4(bh, slot + br * SR + ks * 16 + bhalf);
                ldsm4(bl, slot + (br + 96) * SR + ks * 16 + bhalf);
                // bf16x3: hi*hi + lo*hi + hi*lo
                mma16816(acc[2 * j],     ah, bh[0], bh[1]);
                mma16816(acc[2 * j],     al, bh[0], bh[1]);
                mma16816(acc[2 * j],     ah, bl[0], bl[1]);
                mma16816(acc[2 * j + 1], ah, bh[2], bh[3]);
                mma16816(acc[2 * j + 1], al, bh[2], bh[3]);
                mma16816(acc[2 * j + 1], ah, bl[2], bl[3]);
            }
        }
    }
    asm volatile("cp.async.wait_group 0;" ::: "memory");
    __syncthreads();

    // ---- epilogue: accumulators -> smem gi/gh, then pointwise GRU ---------
    float* sGI = (float*)sbase;          // 64 x 96
    float* sGH = sGI + 64 * 96;          // 64 x 96
    {
        float* dstbuf = wp ? sGH : sGI;
        int g  = lane >> 2;
        int t4 = lane & 3;
#pragma unroll
        for (int j = 0; j < 6; ++j) {
            int col = wn * 48 + j * 8 + t4 * 2;
            int r0  = wm * 16 + g;
            dstbuf[r0 * 96 + col]           = acc[j][0];
            dstbuf[r0 * 96 + col + 1]       = acc[j][1];
            dstbuf[(r0 + 8) * 96 + col]     = acc[j][2];
            dstbuf[(r0 + 8) * 96 + col + 1] = acc[j][3];
        }
    }
    __syncthreads();

    const int lG = l * 3 * HID;
    const float* bihp = bih + lG;
    const float* bhhp = bhh + lG;
    const float* hsrc = g_h + ((size_t)l * 2 + par) * BH;
    float*       hdst = g_h + ((size_t)l * 2 + (par ^ 1)) * BH;
    bf16* hhid = g_hhi + ((size_t)l * 2 + (par ^ 1)) * BH;
    bf16* hlod = g_hlo + ((size_t)l * 2 + (par ^ 1)) * BH;

#pragma unroll
    for (int it = 0; it < 4; ++it) {
        int idx = it * 512 + tid;
        int b = idx >> 5, u = idx & 31;
        int ug = u0 + u;
        float gi_r = sGI[b * 96 + u],       gh_r = sGH[b * 96 + u];
        float gi_z = sGI[b * 96 + 32 + u],  gh_z = sGH[b * 96 + 32 + u];
        float gi_n = sGI[b * 96 + 64 + u],  gh_n = sGH[b * 96 + 64 + u];
        float pr = gi_r + bihp[ug]           + gh_r + bhhp[ug];
        float pz = gi_z + bihp[HID + ug]     + gh_z + bhhp[HID + ug];
        float rg = 1.f / (1.f + __expf(-pr));
        float zg = 1.f / (1.f + __expf(-pz));
        float nn = tanhf(gi_n + bihp[2 * HID + ug] + rg * (gh_n + bhhp[2 * HID + ug]));
        float hold = hsrc[(size_t)b * HID + ug];
        float hn = (1.f - zg) * nn + zg * hold;
        hdst[(size_t)b * HID + ug] = hn;
        bf16 hi, lo;
        split2(hn, hi, lo);
        hhid[(size_t)b * HID + ug] = hi;
        hlod[(size_t)b * HID + ug] = lo;
        if (l == LAYERS - 1)
            out[(size_t)t * BH + (size_t)b * HID + ug] = hn;
    }
}

// ---------------- launch -----------------------------------------------------
extern "C" void kernel_launch(void* const* d_in, const int* in_sizes, int n_in,
                              void* d_out, int out_size)
{
    const float* x   = (const float*)d_in[0];
    const float* h0  = (const float*)d_in[1];
    const float* wih = (const float*)d_in[2];
    const float* whh = (const float*)d_in[3];
    const float* bih = (const float*)d_in[4];
    const float* bhh = (const float*)d_in[5];
    float* out = (float*)d_out;

    cudaFuncSetAttribute(gru_step_kernel,
                         cudaFuncAttributeMaxDynamicSharedMemorySize, SMEM_REQ);

    {
        size_t n = (size_t)LAYERS * 3 * HID * HID;
        split_weights_kernel<<<(unsigned)((n + 255) / 256), 256>>>(wih, whh);
    }
    {
        size_t n = (size_t)S_LEN * BH;
        split_x_kernel<<<(unsigned)((n + 255) / 256), 256>>>(x);
    }
    {
        size_t n = (size_t)LAYERS * BH;
        init_h_kernel<<<(unsigned)((n + 255) / 256), 256>>>(h0);
    }
    for (int gs = 0; gs < S_LEN + LAYERS - 1; ++gs)
        gru_step_kernel<<<dim3(NTILE, LAYERS), 512, SMEM_REQ>>>(gs, bih, bhh, out);
}